// round 5
// baseline (speedup 1.0000x reference)
#include <cuda_runtime.h>
#include <cstdint>

#define B_  8192
#define T_  16
#define K_  512
#define D_  128
#define BM  64          // rows (b) per CTA
#define KC  64          // codes per k-chunk
#define LDT 68          // padded smem row length (floats)
#define NCHUNK (K_/KC)  // 8
#define NCTA1 ((B_/BM)*T_)  // 2048
#define SMEM_BYTES (2*D_*LDT*4)  // zT + cT = 69632 B

#define NZQ  (B_*T_*D_)     // 16777216
#define NTOK (B_*T_)        // 131072

__device__ int            g_tokens[NTOK];
__device__ float          g_cnorm[T_*K_];
__device__ unsigned char  g_used[T_*K_];
__device__ float          g_partial[NCTA1];

// ---------------- f32x2 packed helpers (Blackwell dual-fp32 pipe) ----------------
__device__ __forceinline__ unsigned long long fma2(unsigned long long a,
                                                   unsigned long long b,
                                                   unsigned long long c) {
    unsigned long long d;
    asm("fma.rn.f32x2 %0, %1, %2, %3;" : "=l"(d) : "l"(a), "l"(b), "l"(c));
    return d;
}
__device__ __forceinline__ unsigned long long bcast2(float x) {
    unsigned long long d; unsigned u = __float_as_uint(x);
    asm("mov.b64 %0, {%1, %1};" : "=l"(d) : "r"(u));
    return d;
}
__device__ __forceinline__ unsigned long long packf2(float lo, float hi) {
    unsigned long long d; unsigned a = __float_as_uint(lo), b = __float_as_uint(hi);
    asm("mov.b64 %0, {%1, %2};" : "=l"(d) : "r"(a), "r"(b));
    return d;
}
__device__ __forceinline__ float2 unpk2(unsigned long long v) {
    unsigned lo, hi;
    asm("mov.b64 {%0, %1}, %2;" : "=r"(lo), "=r"(hi) : "l"(v));
    float2 r; r.x = __uint_as_float(lo); r.y = __uint_as_float(hi); return r;
}

// ---------------- prep: codebook norms + clear used bitmap ----------------
__global__ void k_prep(const float* __restrict__ cb) {
    int gt = blockIdx.x * blockDim.x + threadIdx.x;
    int w = gt >> 5, lane = gt & 31;                  // one warp per (t,k) row
    const float4* row = (const float4*)(cb + (size_t)w * D_);
    float4 v = row[lane];
    float s = v.x*v.x + v.y*v.y + v.z*v.z + v.w*v.w;
    #pragma unroll
    for (int o = 16; o; o >>= 1) s += __shfl_xor_sync(0xffffffffu, s, o);
    if (lane == 0) { g_cnorm[w] = s; g_used[w] = 0; }
}

// ---------------- transposed tile loader: dst[d*LDT + r] = src[r*stride + d] ----------------
__device__ __forceinline__ void load_tile_T(float* dst, const float* __restrict__ src,
                                            int src_stride /*floats*/) {
    int tid = threadIdx.x;
    int w = tid >> 5, l = tid & 31;
    int d4 = 4 * w + (l >> 3);   // 0..31 -> d = 4*d4
    int r0 = l & 7;
    #pragma unroll
    for (int r = r0; r < BM; r += 8) {
        float4 v = *(const float4*)(src + (size_t)r * src_stride + 4 * d4);
        dst[(4*d4 + 0) * LDT + r] = v.x;
        dst[(4*d4 + 1) * LDT + r] = v.y;
        dst[(4*d4 + 2) * LDT + r] = v.z;
        dst[(4*d4 + 3) * LDT + r] = v.w;
    }
}

// ---------------- main: fused GEMM + argmin (reference-exact distance) ----------------
__global__ void __launch_bounds__(256, 3) k_main(const float* __restrict__ ze,
                                                 const float* __restrict__ cb) {
    extern __shared__ float sm[];
    float* zT = sm;                 // [128][LDT] : zT[d][r]
    float* cT = sm + D_ * LDT;      // [128][LDT] : cT[d][k]
    __shared__ float red[BM];
    __shared__ float znrow[BM];     // ||z||^2 per local row

    const int tid = threadIdx.x;
    const int bx = blockIdx.x;      // b tile
    const int t  = blockIdx.y;      // 0..15
    const int ty = tid >> 4;        // rows 4*ty..4*ty+3
    const int tx = tid & 15;        // codes 4*tx..4*tx+3 within chunk

    load_tile_T(zT, ze + ((size_t)(bx * BM) * T_ + t) * D_, T_ * D_);
    __syncthreads();

    // per-row ||z||^2 BEFORE the argmin loop (enters the distance formula)
    #pragma unroll
    for (int r = 0; r < 4; r++) {
        int row = 4 * ty + r;
        float zn = 0.f;
        for (int d = tx; d < D_; d += 16) {
            float z = zT[d * LDT + row];
            zn = fmaf(z, z, zn);
        }
        #pragma unroll
        for (int off = 8; off >= 1; off >>= 1)
            zn += __shfl_xor_sync(0xffffffffu, zn, off);
        if (tx == 0) znrow[row] = zn;
    }

    float bestv[4] = {3.4e38f, 3.4e38f, 3.4e38f, 3.4e38f};
    int   bidx[4]  = {0, 0, 0, 0};

    for (int kc = 0; kc < NCHUNK; kc++) {
        __syncthreads();   // protect cT reuse; first iter: covers znrow publish
        load_tile_T(cT, cb + ((size_t)(t * K_ + kc * KC)) * D_, D_);
        __syncthreads();

        unsigned long long acc[4][2];
        #pragma unroll
        for (int r = 0; r < 4; r++) { acc[r][0] = 0ull; acc[r][1] = 0ull; }

        const float* zp = zT + 4 * ty;
        const float* cp = cT + 4 * tx;
        #pragma unroll 4
        for (int d = 0; d < D_; d++) {   // strict in-order fp32 FMA chain per (r,k)
            float4 zv = *(const float4*)(zp + d * LDT);
            float4 cv = *(const float4*)(cp + d * LDT);
            unsigned long long c01 = packf2(cv.x, cv.y);
            unsigned long long c23 = packf2(cv.z, cv.w);
            unsigned long long z0 = bcast2(zv.x), z1 = bcast2(zv.y);
            unsigned long long z2 = bcast2(zv.z), z3 = bcast2(zv.w);
            acc[0][0] = fma2(z0, c01, acc[0][0]);  acc[0][1] = fma2(z0, c23, acc[0][1]);
            acc[1][0] = fma2(z1, c01, acc[1][0]);  acc[1][1] = fma2(z1, c23, acc[1][1]);
            acc[2][0] = fma2(z2, c01, acc[2][0]);  acc[2][1] = fma2(z2, c23, acc[2][1]);
            acc[3][0] = fma2(z3, c01, acc[3][0]);  acc[3][1] = fma2(z3, c23, acc[3][1]);
        }

        const int kb = kc * KC + 4 * tx;
        const float cn0 = g_cnorm[t * K_ + kb + 0];
        const float cn1 = g_cnorm[t * K_ + kb + 1];
        const float cn2 = g_cnorm[t * K_ + kb + 2];
        const float cn3 = g_cnorm[t * K_ + kb + 3];
        #pragma unroll
        for (int r = 0; r < 4; r++) {
            float zn = znrow[4 * ty + r];
            float2 s01 = unpk2(acc[r][0]);
            float2 s23 = unpk2(acc[r][1]);
            // reference formula order: (||z||^2 - 2*s) + ||c||^2, fp32 each step
            float v0 = (zn - 2.f * s01.x) + cn0;
            float v1 = (zn - 2.f * s01.y) + cn1;
            float v2 = (zn - 2.f * s23.x) + cn2;
            float v3 = (zn - 2.f * s23.y) + cn3;
            float bv = v0; int bi = kb;
            if (v1 < bv) { bv = v1; bi = kb + 1; }
            if (v2 < bv) { bv = v2; bi = kb + 2; }
            if (v3 < bv) { bv = v3; bi = kb + 3; }
            #pragma unroll
            for (int off = 8; off >= 1; off >>= 1) {   // lowest-index tie-break
                float ov = __shfl_xor_sync(0xffffffffu, bv, off);
                int   oi = __shfl_xor_sync(0xffffffffu, bi, off);
                if (ov < bv || (ov == bv && oi < bi)) { bv = ov; bi = oi; }
            }
            if (bv < bestv[r] || (bv == bestv[r] && bi < bidx[r])) { bestv[r] = bv; bidx[r] = bi; }
        }
    }

    #pragma unroll
    for (int r = 0; r < 4; r++) {
        if (tx == 0) {
            int row = 4 * ty + r;
            int b = bx * BM + row;
            g_tokens[b * T_ + t] = bidx[r];
            g_used[t * K_ + bidx[r]] = 1;
            red[row] = bestv[r];          // d_best = ||z - c*||^2 (+ tiny fp noise)
        }
    }
    __syncthreads();
    if (tid == 0) {
        float s = 0.f;
        #pragma unroll 8
        for (int i = 0; i < BM; i++) s += red[i];
        g_partial[blockIdx.y * (B_ / BM) + bx] = s;
    }
}

// ---------------- z_q_st = z_e + (z_q - z_e), elementwise fp32 (reference-exact) ----------------
__global__ void k_copy(const float* __restrict__ ze, const float* __restrict__ cb,
                       float* __restrict__ out) {
    int row  = blockIdx.x * 8 + (threadIdx.x >> 5);   // row = b*T_ + t
    int lane = threadIdx.x & 31;
    int t = row & (T_ - 1);
    int tok = g_tokens[row];
    const float4* csrc = (const float4*)(cb + ((size_t)(t * K_ + tok)) * D_);
    const float4* zsrc = (const float4*)(ze + (size_t)row * D_);
    float4* dst = (float4*)(out + (size_t)row * D_);
    float4 c = csrc[lane];
    float4 z = zsrc[lane];
    float4 o;
    o.x = z.x + (c.x - z.x);
    o.y = z.y + (c.y - z.y);
    o.z = z.z + (c.z - z.z);
    o.w = z.w + (c.w - z.w);
    dst[lane] = o;
    if (lane == 0) out[NZQ + row] = (float)tok;
}

// ---------------- scalars: loss + utilization ----------------
__global__ void k_final(float* __restrict__ out) {
    __shared__ double ds[256];
    __shared__ int    dc[256];
    int tid = threadIdx.x;
    double s = 0.0;
    for (int i = tid; i < NCTA1; i += 256) s += (double)g_partial[i];
    int c = 0;
    for (int i = tid; i < T_ * K_; i += 256) c += g_used[i];
    ds[tid] = s; dc[tid] = c;
    __syncthreads();
    if (tid == 0) {
        double ts = 0.0; int tc = 0;
        for (int i = 0; i < 256; i++) { ts += ds[i]; tc += dc[i]; }
        out[NZQ + NTOK + 0] = (float)(0.25 * ts / (double)NZQ);
        out[NZQ + NTOK + 1] = (float)tc / (float)(T_ * K_);
    }
}

extern "C" void kernel_launch(void* const* d_in, const int* in_sizes, int n_in,
                              void* d_out, int out_size) {
    const float* ze = (const float*)d_in[0];
    const float* cb = (const float*)d_in[1];
    float* out = (float*)d_out;

    cudaFuncSetAttribute(k_main, cudaFuncAttributeMaxDynamicSharedMemorySize, SMEM_BYTES);

    k_prep<<<1024, 256>>>(cb);
    dim3 g1(B_ / BM, T_);
    k_main<<<g1, 256, SMEM_BYTES>>>(ze, cb);
    k_copy<<<NTOK / 8, 256>>>(ze, cb, out);
    k_final<<<1, 256>>>(out);
}

// round 7
// speedup vs baseline: 1.2917x; 1.2917x over previous
#include <cuda_runtime.h>
#include <cuda_bf16.h>
#include <cstdint>

#define B_   8192
#define T_   16
#define K_   512
#define D_   128
#define NZQ  (B_*T_*D_)      // 16777216
#define NTOK (B_*T_)         // 131072
#define EPS  1e-4f
#define FINF 3.4e38f

// ---------------- device globals (no allocs allowed) ----------------
__device__ __nv_bfloat16 g_cbh[T_*K_*D_];   // 2MB codebook hi split
__device__ __nv_bfloat16 g_cbl[T_*K_*D_];   // 2MB codebook lo split
__device__ float         g_cnorm[T_*K_];
__device__ int           g_tokens[NTOK];
__device__ unsigned char g_used[T_*K_];
__device__ float         g_partial2[NTOK/8];
__device__ int           g_amb[NTOK];
__device__ int           g_amb_count;

// ---------------- PTX helpers (all legal on base compute_103) ----------------
__device__ __forceinline__ uint32_t smem_to_u32(const void* p) {
    uint32_t a;
    asm("{ .reg .u64 t; cvta.to.shared.u64 t, %1; cvt.u32.u64 %0, t; }" : "=r"(a) : "l"(p));
    return a;
}
__device__ __forceinline__ void ldsm4(uint32_t* r, uint32_t addr) {
    asm volatile("ldmatrix.sync.aligned.m8n8.x4.shared.b16 {%0,%1,%2,%3}, [%4];"
                 : "=r"(r[0]), "=r"(r[1]), "=r"(r[2]), "=r"(r[3]) : "r"(addr));
}
__device__ __forceinline__ void mma16816(float* d, const uint32_t* a, const uint32_t* b) {
    asm volatile("mma.sync.aligned.m16n8k16.row.col.f32.bf16.bf16.f32 "
                 "{%0,%1,%2,%3}, {%4,%5,%6,%7}, {%8,%9}, {%0,%1,%2,%3};"
                 : "+f"(d[0]), "+f"(d[1]), "+f"(d[2]), "+f"(d[3])
                 : "r"(a[0]), "r"(a[1]), "r"(a[2]), "r"(a[3]), "r"(b[0]), "r"(b[1]));
}
// (m1,k1,m2) merge with lowest-index tie-break
__device__ __forceinline__ void tmerge(float& m1, int& k1, float& m2,
                                       float vm1, int vk1, float vm2) {
    if (vm1 < m1 || (vm1 == m1 && vk1 < k1)) {
        m2 = fminf(m1, vm2); m1 = vm1; k1 = vk1;
    } else {
        m2 = fminf(m2, vm1);
    }
}

struct alignas(16) BH8 { __nv_bfloat16 v[8]; };
struct alignas(8)  BH4 { __nv_bfloat16 v[4]; };

// ---------------- k_prep: codebook norms + bf16 hi/lo splits + clears ----------------
__global__ void k_prep(const float* __restrict__ cb) {
    int gt = blockIdx.x * blockDim.x + threadIdx.x;
    int w = gt >> 5, lane = gt & 31;                  // one warp per (t,k) row
    const float4* row = (const float4*)(cb + (size_t)w * D_);
    float4 v = row[lane];
    BH4 h, l;
    float zf[4] = {v.x, v.y, v.z, v.w};
    #pragma unroll
    for (int i = 0; i < 4; i++) {
        h.v[i] = __float2bfloat16_rn(zf[i]);
        l.v[i] = __float2bfloat16_rn(zf[i] - __bfloat162float(h.v[i]));
    }
    *(uint2*)(g_cbh + (size_t)w * D_ + lane * 4) = *(uint2*)&h;
    *(uint2*)(g_cbl + (size_t)w * D_ + lane * 4) = *(uint2*)&l;
    float s = v.x*v.x + v.y*v.y + v.z*v.z + v.w*v.w;
    #pragma unroll
    for (int o = 16; o; o >>= 1) s += __shfl_xor_sync(0xffffffffu, s, o);
    if (lane == 0) { g_cnorm[w] = s; g_used[w] = 0; }
    if (gt == 0) g_amb_count = 0;
}

// ---------------- k_mma: mma.sync bf16x2-split GEMM + argmin ----------------
// smem: padded rows of 272B (128 bf16 + 16B pad) -> conflict-free LDSM
#define LDB   272
#define OFF_CN   0
#define OFF_AH   2048
#define OFF_AL   (OFF_AH + 128*LDB)     // 36864
#define OFF_BH   (OFF_AL + 128*LDB)     // 71680
#define OFF_BL   (OFF_BH + 128*LDB)     // 106496
#define OFF_RM1  (OFF_BL + 128*LDB)     // 141312
#define OFF_RM2  (OFF_RM1 + 128*2*4)
#define OFF_RK1  (OFF_RM2 + 128*2*4)
#define SMEM_MMA (OFF_RK1 + 128*2*4)    // 144384

__global__ void __launch_bounds__(256, 1) k_mma(const float* __restrict__ ze) {
    extern __shared__ char sm[];
    const uint32_t smem_base = smem_to_u32(sm);
    float* cn_s   = (float*)(sm + OFF_CN);
    float* red_m1 = (float*)(sm + OFF_RM1);
    float* red_m2 = (float*)(sm + OFF_RM2);
    int*   red_k1 = (int*)  (sm + OFF_RK1);

    const int tid = threadIdx.x, wid = tid >> 5, l = tid & 31;
    const int wm = wid >> 1, wn = wid & 1;            // 4 x 2 warp grid
    const int bx = blockIdx.x, t = blockIdx.y;

    // stage codebook norms
    for (int i = tid; i < K_; i += 256) cn_s[i] = g_cnorm[t * K_ + i];

    // A tile: 128 z-rows fp32 -> (zh, zl) bf16 padded rows
    const float* zbase = ze + ((size_t)(bx * 128) * T_ + t) * D_;
    for (int G = tid; G < 2048; G += 256) {
        int m = G >> 4, seg = G & 15;
        const float4* p = (const float4*)(zbase + (size_t)m * (T_ * D_) + seg * 8);
        float4 a = p[0], b = p[1];
        float zf[8] = {a.x, a.y, a.z, a.w, b.x, b.y, b.z, b.w};
        BH8 h, lo;
        #pragma unroll
        for (int i = 0; i < 8; i++) {
            h.v[i]  = __float2bfloat16_rn(zf[i]);
            lo.v[i] = __float2bfloat16_rn(zf[i] - __bfloat162float(h.v[i]));
        }
        *(uint4*)(sm + OFF_AH + m * LDB + seg * 16) = *(uint4*)&h;
        *(uint4*)(sm + OFF_AL + m * LDB + seg * 16) = *(uint4*)&lo;
    }

    // running per-row argmin state (thread tid < 128 owns local row = tid)
    float run_m1 = FINF, run_m2 = FINF; int run_k1 = 0;

    // LDSM base addresses
    const uint32_t aAddrH = smem_base + OFF_AH + (wm*32 + (l & 15)) * LDB + ((l >> 4) * 8) * 2;
    const uint32_t aAddrL = aAddrH + (OFF_AL - OFF_AH);
    const int nofs = (l & 7) + ((l >> 4) & 1) * 8;
    const int kofs = ((l >> 3) & 1) * 8;
    const uint32_t bAddrH = smem_base + OFF_BH + (wn*64 + nofs) * LDB + kofs * 2;
    const uint32_t bAddrL = bAddrH + (OFF_BL - OFF_BH);

    for (int c = 0; c < 4; c++) {
        __syncthreads();   // previous chunk's LDSM done; B buffer reusable (also covers A/cn on c=0)
        // load B chunk (128 codes x 128 d, hi+lo) into padded smem rows
        {
            const char* sh = (const char*)(g_cbh + ((size_t)(t * K_ + c * 128)) * D_);
            const char* sl = (const char*)(g_cbl + ((size_t)(t * K_ + c * 128)) * D_);
            for (int G = tid; G < 2048; G += 256) {
                int n = G >> 4, seg = G & 15;
                *(uint4*)(sm + OFF_BH + n * LDB + seg * 16) = *(const uint4*)(sh + (size_t)n * 256 + seg * 16);
                *(uint4*)(sm + OFF_BL + n * LDB + seg * 16) = *(const uint4*)(sl + (size_t)n * 256 + seg * 16);
            }
        }
        __syncthreads();

        float acc[2][8][4];
        #pragma unroll
        for (int mi = 0; mi < 2; mi++)
            #pragma unroll
            for (int ni = 0; ni < 8; ni++)
                #pragma unroll
                for (int j = 0; j < 4; j++) acc[mi][ni][j] = 0.f;

        #pragma unroll 1
        for (int ks = 0; ks < 8; ks++) {
            uint32_t aH[2][4], aL[2][4], bH[4][4], bL[4][4];
            ldsm4(aH[0], aAddrH + ks * 32);
            ldsm4(aH[1], aAddrH + 16 * LDB + ks * 32);
            ldsm4(aL[0], aAddrL + ks * 32);
            ldsm4(aL[1], aAddrL + 16 * LDB + ks * 32);
            #pragma unroll
            for (int p = 0; p < 4; p++) {
                ldsm4(bH[p], bAddrH + p * 16 * LDB + ks * 32);
                ldsm4(bL[p], bAddrL + p * 16 * LDB + ks * 32);
            }
            #pragma unroll
            for (int mi = 0; mi < 2; mi++)
                #pragma unroll
                for (int p = 0; p < 4; p++) {
                    mma16816(acc[mi][2*p],   aH[mi], &bH[p][0]);   // zh.ch
                    mma16816(acc[mi][2*p+1], aH[mi], &bH[p][2]);
                    mma16816(acc[mi][2*p],   aH[mi], &bL[p][0]);   // zh.cl
                    mma16816(acc[mi][2*p+1], aH[mi], &bL[p][2]);
                    mma16816(acc[mi][2*p],   aL[mi], &bH[p][0]);   // zl.ch
                    mma16816(acc[mi][2*p+1], aL[mi], &bH[p][2]);
                }
        }

        // per-chunk argmin epilogue: v = cn[k] - 2*s
        const int g = l >> 2, q = l & 3;
        #pragma unroll
        for (int mi = 0; mi < 2; mi++) {
            #pragma unroll
            for (int half = 0; half < 2; half++) {
                float m1 = FINF, m2 = FINF; int k1 = 0;
                #pragma unroll
                for (int ni = 0; ni < 8; ni++) {
                    #pragma unroll
                    for (int j = 0; j < 2; j++) {
                        int k = c*128 + wn*64 + ni*8 + 2*q + j;
                        float v = fmaf(-2.f, acc[mi][ni][half*2 + j], cn_s[k]);
                        if (v < m1)      { m2 = m1; m1 = v; k1 = k; }
                        else if (v < m2) { m2 = v; }
                    }
                }
                #pragma unroll
                for (int o = 1; o <= 2; o <<= 1) {    // merge across the 4 lanes of a row
                    float om1 = __shfl_xor_sync(0xffffffffu, m1, o);
                    int   ok1 = __shfl_xor_sync(0xffffffffu, k1, o);
                    float om2 = __shfl_xor_sync(0xffffffffu, m2, o);
                    tmerge(m1, k1, m2, om1, ok1, om2);
                }
                if (q == 0) {
                    int rowl = wm*32 + mi*16 + half*8 + g;
                    red_m1[rowl*2 + wn] = m1;
                    red_m2[rowl*2 + wn] = m2;
                    red_k1[rowl*2 + wn] = k1;
                }
            }
        }
        __syncthreads();
        if (tid < 128) {
            tmerge(run_m1, run_k1, run_m2, red_m1[tid*2+0], red_k1[tid*2+0], red_m2[tid*2+0]);
            tmerge(run_m1, run_k1, run_m2, red_m1[tid*2+1], red_k1[tid*2+1], red_m2[tid*2+1]);
        }
    }

    if (tid < 128) {
        int row = (bx * 128 + tid) * T_ + t;
        g_tokens[row] = run_k1;
        if (run_m2 - run_m1 < EPS) {
            int idx = atomicAdd(&g_amb_count, 1);
            g_amb[idx] = row;
        }
    }
}

// ---------------- k_fix: exact fp32 rescan of ambiguous rows (reference formula) ----------------
__global__ void __launch_bounds__(256) k_fix(const float* __restrict__ ze,
                                             const float* __restrict__ cb) {
    __shared__ float zb[8][128];
    const int wid = threadIdx.x >> 5, lane = threadIdx.x & 31;
    const int gw = blockIdx.x * 8 + wid;
    const int nw = gridDim.x * 8;
    const int cnt = g_amb_count;
    for (int i = gw; i < cnt; i += nw) {
        int row = g_amb[i];
        int t = row & (T_ - 1);
        const float4* z4 = (const float4*)(ze + (size_t)row * D_);
        float4 zv = z4[lane];
        ((float4*)zb[wid])[lane] = zv;
        float zn = fmaf(zv.w, zv.w, fmaf(zv.z, zv.z, fmaf(zv.y, zv.y, zv.x * zv.x)));
        #pragma unroll
        for (int o = 16; o; o >>= 1) zn += __shfl_xor_sync(0xffffffffu, zn, o);
        __syncwarp();

        float bv = FINF; int bi = 0;
        for (int j = 0; j < 16; j++) {
            int k = j * 32 + lane;
            const float4* crow = (const float4*)(cb + ((size_t)(t * K_ + k)) * D_);
            float s = 0.f;
            #pragma unroll 8
            for (int d4 = 0; d4 < 32; d4++) {        // strict in-order fp32 chain
                float4 cv = crow[d4];
                s = fmaf(zb[wid][4*d4 + 0], cv.x, s);
                s = fmaf(zb[wid][4*d4 + 1], cv.y, s);
                s = fmaf(zb[wid][4*d4 + 2], cv.z, s);
                s = fmaf(zb[wid][4*d4 + 3], cv.w, s);
            }
            float v = (zn - 2.f * s) + g_cnorm[t * K_ + k];   // reference rounding order
            if (v < bv) { bv = v; bi = k; }
        }
        #pragma unroll
        for (int o = 16; o; o >>= 1) {               // lowest-index tie-break
            float ov = __shfl_xor_sync(0xffffffffu, bv, o);
            int   oi = __shfl_xor_sync(0xffffffffu, bi, o);
            if (ov < bv || (ov == bv && oi < bi)) { bv = ov; bi = oi; }
        }
        if (lane == 0) g_tokens[row] = bi;
        __syncwarp();
    }
}

// ---------------- k_copy: z_q_st + tokens + used + exact loss partials ----------------
__global__ void k_copy(const float* __restrict__ ze, const float* __restrict__ cb,
                       float* __restrict__ out) {
    __shared__ float ls[8];
    const int wid = threadIdx.x >> 5, lane = threadIdx.x & 31;
    const int row = blockIdx.x * 8 + wid;
    const int t = row & (T_ - 1);
    const int tok = g_tokens[row];
    const float4* cs = (const float4*)(cb + ((size_t)(t * K_ + tok)) * D_);
    const float4* zs = (const float4*)(ze + (size_t)row * D_);
    float4 c = cs[lane], z = zs[lane];
    float4 o;
    o.x = z.x + (c.x - z.x); o.y = z.y + (c.y - z.y);
    o.z = z.z + (c.z - z.z); o.w = z.w + (c.w - z.w);
    ((float4*)(out + (size_t)row * D_))[lane] = o;
    float dx = z.x - c.x, dy = z.y - c.y, dz = z.z - c.z, dw = z.w - c.w;
    float q = fmaf(dw, dw, fmaf(dz, dz, fmaf(dy, dy, dx * dx)));
    #pragma unroll
    for (int of = 16; of; of >>= 1) q += __shfl_xor_sync(0xffffffffu, q, of);
    if (lane == 0) {
        out[NZQ + row] = (float)tok;
        g_used[t * K_ + tok] = 1;
        ls[wid] = q;
    }
    __syncthreads();
    if (threadIdx.x == 0) {
        float s = 0.f;
        #pragma unroll
        for (int i = 0; i < 8; i++) s += ls[i];
        g_partial2[blockIdx.x] = s;
    }
}

// ---------------- k_final: scalars ----------------
__global__ void k_final(float* __restrict__ out) {
    __shared__ double ds[256];
    __shared__ int    dc[256];
    const int tid = threadIdx.x;
    double s = 0.0;
    for (int i = tid; i < NTOK / 8; i += 256) s += (double)g_partial2[i];
    int c = 0;
    for (int i = tid; i < T_ * K_; i += 256) c += g_used[i];
    ds[tid] = s; dc[tid] = c;
    __syncthreads();
    for (int st = 128; st; st >>= 1) {
        if (tid < st) { ds[tid] += ds[tid + st]; dc[tid] += dc[tid + st]; }
        __syncthreads();
    }
    if (tid == 0) {
        out[NZQ + NTOK + 0] = (float)(0.25 * ds[0] / (double)NZQ);
        out[NZQ + NTOK + 1] = (float)dc[0] / (float)(T_ * K_);
    }
}

extern "C" void kernel_launch(void* const* d_in, const int* in_sizes, int n_in,
                              void* d_out, int out_size) {
    const float* ze = (const float*)d_in[0];
    const float* cb = (const float*)d_in[1];
    float* out = (float*)d_out;

    cudaFuncSetAttribute(k_mma, cudaFuncAttributeMaxDynamicSharedMemorySize, SMEM_MMA);

    k_prep<<<1024, 256>>>(cb);
    dim3 gm(B_ / 128, T_);
    k_mma<<<gm, 256, SMEM_MMA>>>(ze);
    k_fix<<<256, 256>>>(ze, cb);
    k_copy<<<NTOK / 8, 256>>>(ze, cb, out);
    k_final<<<1, 256>>>(out);
}